// round 8
// baseline (speedup 1.0000x reference)
#include <cuda_runtime.h>
#include <cuda_bf16.h>
#include <math.h>
#include <stdint.h>

#define N_NODES 10000
#define MPAD    10112           // 79 * 128 (padded row count, no M guards needed)
#define N_EDGES 160000
#define N_TOT   (N_EDGES + N_NODES)
#define G       64
#define D_IN    1280
#define D_HID   512
#define D_OUT   256
#define SCAN_BLKS 40            // 40 * 256 = 10240 >= N_NODES

// ---------------- scratch (static device globals; no allocation) ----------------
__device__ int   g_deg[N_NODES];
__device__ float g_dis[N_NODES];
__device__ int   g_rowptr[N_NODES + 1];
__device__ int   g_cursor[N_NODES];
__device__ int   g_part[SCAN_BLKS];
__device__ int   g_poff[SCAN_BLKS];
__device__ int   g_col[N_TOT];
__device__ float g_val[N_TOT];
__device__ float g_h1[(size_t)MPAD * D_HID];     // GEMM output (fp32, pre-aggregation)
__device__ float g_h2[(size_t)MPAD * D_HID];     // final-layer aggregate output (fp32)
__device__ __nv_bfloat16 g_xh[(size_t)MPAD * D_IN];   // x split hi
__device__ __nv_bfloat16 g_xl[(size_t)MPAD * D_IN];   // x split lo
__device__ __nv_bfloat16 g_ah[(size_t)MPAD * D_HID];  // activation split hi
__device__ __nv_bfloat16 g_al[(size_t)MPAD * D_HID];  // activation split lo
// weights, transposed [N][K], split hi/lo
__device__ __nv_bfloat16 g_w1h[D_IN * D_HID],  g_w1l[D_IN * D_HID];
__device__ __nv_bfloat16 g_w2h[D_HID * D_HID], g_w2l[D_HID * D_HID];
__device__ __nv_bfloat16 g_w3h[D_HID * D_HID], g_w3l[D_HID * D_HID];
__device__ __nv_bfloat16 g_w4h[D_HID * D_OUT], g_w4l[D_HID * D_OUT];
__device__ float g_pool[G * D_OUT];
__device__ int   g_gcnt[G];
__device__ int   g_goff[G + 1];

// ---------------- graph preprocessing ----------------
__global__ void init_kernel() {
    int i = blockIdx.x * blockDim.x + threadIdx.x;
    if (i < N_NODES) g_deg[i] = 1;       // self loop
    if (i < G) g_gcnt[i] = 0;
}

__global__ void hist_kernel(const int* __restrict__ dst,
                            const int* __restrict__ batch) {
    int e = blockIdx.x * blockDim.x + threadIdx.x;
    if (e < N_EDGES) atomicAdd(&g_deg[dst[e]], 1);
    if (e < N_NODES) atomicAdd(&g_gcnt[batch[e]], 1);
}

// 3-phase exclusive scan of g_deg -> g_rowptr
__global__ void scan_part_kernel() {
    __shared__ int sdata[256];
    int t = threadIdx.x;
    int i = blockIdx.x * 256 + t;
    int v = (i < N_NODES) ? g_deg[i] : 0;
    sdata[t] = v;
    __syncthreads();
#pragma unroll
    for (int off = 1; off < 256; off <<= 1) {
        int tmp = (t >= off) ? sdata[t - off] : 0;
        __syncthreads();
        sdata[t] += tmp;
        __syncthreads();
    }
    if (i < N_NODES) g_rowptr[i] = sdata[t] - v;   // local exclusive
    if (t == 255) g_part[blockIdx.x] = sdata[255];
}

// parallel mid scan: threads 0-63 scan g_part (40 padded), 64-127 scan g_gcnt (64)
__global__ void scan_mid_kernel() {
    __shared__ int sa[64], sb[64];
    int t = threadIdx.x;
    int v0 = 0;
    if (t < 64) { v0 = (t < SCAN_BLKS) ? g_part[t] : 0; sa[t] = v0; }
    else        { v0 = g_gcnt[t - 64]; sb[t - 64] = v0; }
    __syncthreads();
#pragma unroll
    for (int off = 1; off < 64; off <<= 1) {
        int v = 0;
        if (t < 64) { if (t >= off) v = sa[t - off]; }
        else        { if ((t - 64) >= off) v = sb[t - 64 - off]; }
        __syncthreads();
        if (t < 64) sa[t] += v; else sb[t - 64] += v;
        __syncthreads();
    }
    if (t < SCAN_BLKS) g_poff[t] = sa[t] - v0;                 // exclusive
    if (t >= 64) {
        g_goff[t - 64] = sb[t - 64] - v0;                      // exclusive
        if (t == 127) g_goff[G] = sb[63];
    }
}

__global__ void scan_add_kernel() {
    int t = threadIdx.x;
    int i = blockIdx.x * 256 + t;
    if (i >= N_NODES) return;
    int excl = g_rowptr[i] + g_poff[blockIdx.x];
    g_rowptr[i] = excl;
    g_cursor[i] = excl;
    g_dis[i] = rsqrtf((float)g_deg[i]);
    if (i == 0) g_rowptr[N_NODES] = N_TOT;   // total is a known constant
}

__global__ void fill_csr_kernel(const int* __restrict__ src,
                                const int* __restrict__ dst) {
    int e = blockIdx.x * blockDim.x + threadIdx.x;
    if (e >= N_TOT) return;
    int s, d;
    if (e < N_EDGES) { s = src[e]; d = dst[e]; }
    else             { s = d = e - N_EDGES; }
    int pos = atomicAdd(&g_cursor[d], 1);
    g_col[pos] = s;
    g_val[pos] = g_dis[s] * g_dis[d];
}

// ---------------- bf16 split conversions ----------------
__global__ void wconv_kernel(const float* __restrict__ W, int K, int N, int layer) {
    __nv_bfloat16 *Wh, *Wl;
    switch (layer) {
        case 1: Wh = g_w1h; Wl = g_w1l; break;
        case 2: Wh = g_w2h; Wl = g_w2l; break;
        case 3: Wh = g_w3h; Wl = g_w3l; break;
        default: Wh = g_w4h; Wl = g_w4l; break;
    }
    int idx = blockIdx.x * blockDim.x + threadIdx.x;
    if (idx >= K * N) return;
    int k = idx / N, n = idx - k * N;
    float v = W[idx];
    __nv_bfloat16 h = __float2bfloat16(v);
    __nv_bfloat16 l = __float2bfloat16(v - __bfloat162float(h));
    Wh[(size_t)n * K + k] = h;
    Wl[(size_t)n * K + k] = l;
}

__global__ void xconv_kernel(const float* __restrict__ x) {
    int idx = blockIdx.x * blockDim.x + threadIdx.x;
    if (idx >= N_NODES * D_IN) return;
    float v = x[idx];
    __nv_bfloat16 h = __float2bfloat16(v);
    g_xh[idx] = h;
    g_xl[idx] = __float2bfloat16(v - __bfloat162float(h));
}

// ========== mma.sync GEMM, ldmatrix + batched-fragment schedule ==========
// 3-term bf16 split, fp32 accum. Block 128x128x32, 8 warps (2x4), warp tile 64x32.
// SMEM per stage: 4 tiles (Ah,Al,Bh,Bl) of [2 kchunks][128 rows][16 bf16].
// 16B-half swizzle: physical_half = logical_half ^ ((row>>2)&1).
#define GKB        32
#define TILE_B     8192                  // bytes per tile (2*128*32)
#define STAGE_B    32768                 // 4 tiles
#define SMEM_BYTES (2 * STAGE_B)         // 65536

__device__ __forceinline__ void cp16(uint32_t dst, const void* src) {
    asm volatile("cp.async.cg.shared.global [%0], [%1], 16;" :: "r"(dst), "l"(src));
}

__device__ __forceinline__ void ldsm4(uint32_t r[4], uint32_t addr) {
    asm volatile("ldmatrix.sync.aligned.m8n8.x4.shared.b16 {%0,%1,%2,%3}, [%4];"
                 : "=r"(r[0]), "=r"(r[1]), "=r"(r[2]), "=r"(r[3]) : "r"(addr));
}

__device__ __forceinline__ void mma_bf16(float c[4], const uint32_t a[4],
                                         uint32_t b0, uint32_t b1) {
    asm volatile(
        "mma.sync.aligned.m16n8k16.row.col.f32.bf16.bf16.f32 "
        "{%0,%1,%2,%3}, {%4,%5,%6,%7}, {%8,%9}, {%0,%1,%2,%3};"
        : "+f"(c[0]), "+f"(c[1]), "+f"(c[2]), "+f"(c[3])
        : "r"(a[0]), "r"(a[1]), "r"(a[2]), "r"(a[3]), "r"(b0), "r"(b1));
}

__global__ __launch_bounds__(256, 2) void mma_gemm_kernel(int asel, int layer,
                                                          int K, int N) {
    extern __shared__ char smem[];
    const __nv_bfloat16 *Ah, *Al, *Bh, *Bl;
    if (asel == 0) { Ah = g_xh; Al = g_xl; } else { Ah = g_ah; Al = g_al; }
    switch (layer) {
        case 1: Bh = g_w1h; Bl = g_w1l; break;
        case 2: Bh = g_w2h; Bl = g_w2l; break;
        case 3: Bh = g_w3h; Bl = g_w3l; break;
        default: Bh = g_w4h; Bl = g_w4l; break;
    }
    uint32_t sbase = (uint32_t)__cvta_generic_to_shared(smem);
    int tid = threadIdx.x;
    int brow = blockIdx.y * 128;
    int bcol = blockIdx.x * 128;

    // loader mapping: tid<128 -> hi tiles, tid>=128 -> lo tiles; row = tid&127
    int lrow = tid & 127;
    int lsplit = tid >> 7;
    const __nv_bfloat16* gA = (lsplit ? Al : Ah) + (size_t)(brow + lrow) * K;
    const __nv_bfloat16* gB = (lsplit ? Bl : Bh) + (size_t)(bcol + lrow) * K;
    uint32_t rsw = ((lrow >> 2) & 1);
    uint32_t rowoff = (uint32_t)lrow * 32;

    auto load_stage = [&](int s) {
        int k0 = s * GKB;
        uint32_t stg = sbase + (uint32_t)(s & 1) * STAGE_B;
        uint32_t tA = stg + (uint32_t)lsplit * TILE_B;
        uint32_t tB = stg + (uint32_t)(2 + lsplit) * TILE_B;
#pragma unroll
        for (int kc = 0; kc < 2; kc++) {
#pragma unroll
            for (int hl = 0; hl < 2; hl++) {
                uint32_t doff = (uint32_t)kc * 4096 + rowoff + ((hl ^ rsw) * 16);
                cp16(tA + doff, gA + k0 + kc * 16 + hl * 8);
                cp16(tB + doff, gB + k0 + kc * 16 + hl * 8);
            }
        }
    };

    int warp = tid >> 5, lane = tid & 31;
    int wm = warp >> 2, wn = warp & 3;       // 2 x 4 warp grid
    int group = lane >> 2, quad = lane & 3;
    uint32_t lmoff = (uint32_t)(lane & 15) * 32 +
                     (uint32_t)(((lane >> 4) ^ ((lane >> 2) & 1)) * 16);

    float acc[4][4][4];
#pragma unroll
    for (int i = 0; i < 4; i++)
#pragma unroll
        for (int j = 0; j < 4; j++)
#pragma unroll
            for (int v = 0; v < 4; v++) acc[i][j][v] = 0.f;

    int NS = K / GKB;
    load_stage(0);
    asm volatile("cp.async.commit_group;");

    for (int it = 0; it < NS; it++) {
        if (it + 1 < NS) {
            load_stage(it + 1);
            asm volatile("cp.async.commit_group;");
            asm volatile("cp.async.wait_group 1;");
        } else {
            asm volatile("cp.async.wait_group 0;");
        }
        __syncthreads();

        uint32_t stg = sbase + (uint32_t)(it & 1) * STAGE_B;
#pragma unroll
        for (int kc = 0; kc < 2; kc++) {
            uint32_t kb = (uint32_t)kc * 4096;
            // B fragments first (4 LDSM), reused by all rows
            uint32_t bh[2][4], bl[2][4];
#pragma unroll
            for (int ib = 0; ib < 2; ib++) {
                uint32_t nb = (uint32_t)(wn * 32 + ib * 16) * 32;
                ldsm4(bh[ib], stg + 2 * TILE_B + kb + nb + lmoff);
                ldsm4(bl[ib], stg + 3 * TILE_B + kb + nb + lmoff);
            }
            // A fragments in 2 groups of 2 row-tiles; batch loads, then MMA burst
#pragma unroll
            for (int half = 0; half < 2; half++) {
                uint32_t ah[2][4], al[2][4];
#pragma unroll
                for (int q = 0; q < 2; q++) {
                    uint32_t mb = (uint32_t)(wm * 64 + (half * 2 + q) * 16) * 32;
                    ldsm4(ah[q], stg + kb + mb + lmoff);
                    ldsm4(al[q], stg + TILE_B + kb + mb + lmoff);
                }
#pragma unroll
                for (int q = 0; q < 2; q++) {
                    int im = half * 2 + q;
#pragma unroll
                    for (int jn = 0; jn < 4; jn++) {
                        int ib = jn >> 1, pr = jn & 1;
                        mma_bf16(acc[im][jn], ah[q], bh[ib][pr], bh[ib][pr + 2]);
                        mma_bf16(acc[im][jn], ah[q], bl[ib][pr], bl[ib][pr + 2]);
                        mma_bf16(acc[im][jn], al[q], bh[ib][pr], bh[ib][pr + 2]);
                    }
                }
            }
        }
        __syncthreads();
    }

    // epilogue: rows padded to MPAD, no guards
#pragma unroll
    for (int im = 0; im < 4; im++) {
        int r = brow + wm * 64 + im * 16 + group;
#pragma unroll
        for (int jn = 0; jn < 4; jn++) {
            int c = bcol + wn * 32 + jn * 8 + quad * 2;
            *(float2*)(g_h1 + (size_t)r * N + c) =
                make_float2(acc[im][jn][0], acc[im][jn][1]);
            *(float2*)(g_h1 + (size_t)(r + 8) * N + c) =
                make_float2(acc[im][jn][2], acc[im][jn][3]);
        }
    }
}

// ---------------- aggregation (layers 1-3): bias+relu, write bf16 hi/lo split ----
__global__ void aggregate_bf_kernel(const float* __restrict__ bias) {
    int i = blockIdx.x;
    int t = threadIdx.x;     // 128 threads (D_HID/4)
    int s = g_rowptr[i], e = g_rowptr[i + 1];
    float4 acc = make_float4(0.f, 0.f, 0.f, 0.f);
    const float4* hin4 = (const float4*)g_h1;
    for (int p = s; p < e; p++) {
        int c = g_col[p];
        float v = g_val[p];
        float4 x = hin4[(size_t)c * 128 + t];
        acc.x += v * x.x; acc.y += v * x.y; acc.z += v * x.z; acc.w += v * x.w;
    }
    float4 b = ((const float4*)bias)[t];
    acc.x = fmaxf(acc.x + b.x, 0.f); acc.y = fmaxf(acc.y + b.y, 0.f);
    acc.z = fmaxf(acc.z + b.z, 0.f); acc.w = fmaxf(acc.w + b.w, 0.f);
    __nv_bfloat16 hx = __float2bfloat16(acc.x), hy = __float2bfloat16(acc.y);
    __nv_bfloat16 hz = __float2bfloat16(acc.z), hw = __float2bfloat16(acc.w);
    __nv_bfloat16 lx = __float2bfloat16(acc.x - __bfloat162float(hx));
    __nv_bfloat16 ly = __float2bfloat16(acc.y - __bfloat162float(hy));
    __nv_bfloat16 lz = __float2bfloat16(acc.z - __bfloat162float(hz));
    __nv_bfloat16 lw = __float2bfloat16(acc.w - __bfloat162float(hw));
    __nv_bfloat162* oh = (__nv_bfloat162*)(g_ah + (size_t)i * D_HID);
    __nv_bfloat162* ol = (__nv_bfloat162*)(g_al + (size_t)i * D_HID);
    __nv_bfloat162 p0; p0.x = hx; p0.y = hy;
    __nv_bfloat162 p1; p1.x = hz; p1.y = hw;
    __nv_bfloat162 q0; q0.x = lx; q0.y = ly;
    __nv_bfloat162 q1; q1.x = lz; q1.y = lw;
    oh[t * 2] = p0; oh[t * 2 + 1] = p1;
    ol[t * 2] = q0; ol[t * 2 + 1] = q1;
}

// ---------------- aggregation (layer 4): bias, fp32 out, no relu ----------------
__global__ void aggregate_f32_kernel(const float* __restrict__ bias) {
    int i = blockIdx.x;
    int t = threadIdx.x;     // 64 threads (D_OUT/4)
    int s = g_rowptr[i], e = g_rowptr[i + 1];
    float4 acc = make_float4(0.f, 0.f, 0.f, 0.f);
    const float4* hin4 = (const float4*)g_h1;
    for (int p = s; p < e; p++) {
        int c = g_col[p];
        float v = g_val[p];
        float4 x = hin4[(size_t)c * 64 + t];
        acc.x += v * x.x; acc.y += v * x.y; acc.z += v * x.z; acc.w += v * x.w;
    }
    float4 b = ((const float4*)bias)[t];
    acc.x += b.x; acc.y += b.y; acc.z += b.z; acc.w += b.w;
    ((float4*)g_h2)[(size_t)i * 64 + t] = acc;
}

// ---------------- pooling + L2 normalize (reads g_h2) ----------------
__global__ void pool_kernel() {
    __shared__ float red[256];
    int g = blockIdx.x, t = threadIdx.x;
    int s = g_goff[g], e = g_goff[g + 1];
    float acc = 0.f;
    for (int n = s; n < e; n++) acc += g_h2[(size_t)n * D_OUT + t];
    float cnt = (float)(e - s);
    float mean = acc / fmaxf(cnt, 1.f);
    red[t] = mean * mean;
    __syncthreads();
    for (int off = 128; off > 0; off >>= 1) {
        if (t < off) red[t] += red[t + off];
        __syncthreads();
    }
    float nrm = sqrtf(red[0]);
    g_pool[g * D_OUT + t] = mean / fmaxf(nrm, 1e-12f);
}

// ---------------- classifier MLP head ----------------
__global__ void mlp_kernel(const float* __restrict__ vec,
                           const float* __restrict__ cW1, const float* __restrict__ cb1,
                           const float* __restrict__ cW2, const float* __restrict__ cb2,
                           const float* __restrict__ cW3, const float* __restrict__ cb3,
                           float* __restrict__ out) {
    __shared__ float comb[512];
    __shared__ float z1[256];
    __shared__ float z2[64];
    int g = blockIdx.x, t = threadIdx.x;   // 256 threads
    comb[t] = g_pool[g * 256 + t];
    comb[256 + t] = vec[g * 256 + t];
    __syncthreads();
    float s1 = cb1[t];
    for (int k = 0; k < 512; k++) s1 += comb[k] * cW1[k * 256 + t];
    z1[t] = fmaxf(s1, 0.f);
    __syncthreads();
    if (t < 64) {
        float s2 = cb2[t];
        for (int k = 0; k < 256; k++) s2 += z1[k] * cW2[k * 64 + t];
        z2[t] = fmaxf(s2, 0.f);
    }
    __syncthreads();
    if (t == 0) {
        float s3 = cb3[0];
        for (int k = 0; k < 64; k++) s3 += z2[k] * cW3[k];
        out[g] = 1.f / (1.f + expf(-s3));
    }
}

// ---------------- launch ----------------
extern "C" void kernel_launch(void* const* d_in, const int* in_sizes, int n_in,
                              void* d_out, int out_size) {
    const float* x    = (const float*)d_in[0];
    const int*   ei   = (const int*)d_in[1];   // [2, E] int32
    const int*   bat  = (const int*)d_in[2];
    const float* vec  = (const float*)d_in[3];
    const float* W1 = (const float*)d_in[4],  *b1 = (const float*)d_in[5];
    const float* W2 = (const float*)d_in[6],  *b2 = (const float*)d_in[7];
    const float* W3 = (const float*)d_in[8],  *b3 = (const float*)d_in[9];
    const float* W4 = (const float*)d_in[10], *b4 = (const float*)d_in[11];
    const float* cW1 = (const float*)d_in[12], *cb1 = (const float*)d_in[13];
    const float* cW2 = (const float*)d_in[14], *cb2 = (const float*)d_in[15];
    const float* cW3 = (const float*)d_in[16], *cb3 = (const float*)d_in[17];
    float* out = (float*)d_out;

    const int* src = ei;
    const int* dst = ei + N_EDGES;

    cudaFuncSetAttribute(mma_gemm_kernel,
                         cudaFuncAttributeMaxDynamicSharedMemorySize, SMEM_BYTES);

    // graph preprocessing (3-phase scan, all-SM parallel)
    init_kernel<<<(N_NODES + 255) / 256, 256>>>();
    hist_kernel<<<(N_EDGES + 255) / 256, 256>>>(dst, bat);
    scan_part_kernel<<<SCAN_BLKS, 256>>>();
    scan_mid_kernel<<<1, 128>>>();
    scan_add_kernel<<<SCAN_BLKS, 256>>>();
    fill_csr_kernel<<<(N_TOT + 255) / 256, 256>>>(src, dst);

    // conversions
    wconv_kernel<<<(D_IN * D_HID + 255) / 256, 256>>>(W1, D_IN, D_HID, 1);
    wconv_kernel<<<(D_HID * D_HID + 255) / 256, 256>>>(W2, D_HID, D_HID, 2);
    wconv_kernel<<<(D_HID * D_HID + 255) / 256, 256>>>(W3, D_HID, D_HID, 3);
    wconv_kernel<<<(D_HID * D_OUT + 255) / 256, 256>>>(W4, D_HID, D_OUT, 4);
    xconv_kernel<<<(N_NODES * D_IN + 255) / 256, 256>>>(x);

    dim3 blk(256);
    int gy = MPAD / 128;   // 79
    // layer 1
    mma_gemm_kernel<<<dim3(D_HID / 128, gy), blk, SMEM_BYTES>>>(0, 1, D_IN, D_HID);
    aggregate_bf_kernel<<<N_NODES, 128>>>(b1);
    // layer 2
    mma_gemm_kernel<<<dim3(D_HID / 128, gy), blk, SMEM_BYTES>>>(1, 2, D_HID, D_HID);
    aggregate_bf_kernel<<<N_NODES, 128>>>(b2);
    // layer 3
    mma_gemm_kernel<<<dim3(D_HID / 128, gy), blk, SMEM_BYTES>>>(1, 3, D_HID, D_HID);
    aggregate_bf_kernel<<<N_NODES, 128>>>(b3);
    // layer 4
    mma_gemm_kernel<<<dim3(D_OUT / 128, gy), blk, SMEM_BYTES>>>(1, 4, D_HID, D_OUT);
    aggregate_f32_kernel<<<N_NODES, 64>>>(b4);

    // pooling + normalize + head
    pool_kernel<<<G, 256>>>();
    mlp_kernel<<<G, 256>>>(vec, cW1, cb1, cW2, cb2, cW3, cb3, out);
}

// round 9
// speedup vs baseline: 1.2687x; 1.2687x over previous
#include <cuda_runtime.h>
#include <cuda_bf16.h>
#include <math.h>
#include <stdint.h>

#define N_NODES 10000
#define MPAD    10112           // 79 * 128 (padded row count, no M guards needed)
#define N_EDGES 160000
#define N_TOT   (N_EDGES + N_NODES)
#define G       64
#define D_IN    1280
#define D_HID   512
#define D_OUT   256
#define SCAN_BLKS 40            // 40 * 256 = 10240 >= N_NODES

// ---------------- scratch (static device globals; no allocation) ----------------
__device__ int   g_deg[N_NODES];
__device__ float g_dis[N_NODES];
__device__ int   g_rowptr[N_NODES + 1];
__device__ int   g_cursor[N_NODES];
__device__ int   g_part[SCAN_BLKS];
__device__ int   g_poff[SCAN_BLKS];
__device__ int   g_col[N_TOT];
__device__ float g_val[N_TOT];
__device__ float g_h1[(size_t)MPAD * D_HID];     // GEMM output (fp32, pre-aggregation)
__device__ float g_h2[(size_t)MPAD * D_HID];     // final-layer aggregate output (fp32)
__device__ __nv_bfloat16 g_xh[(size_t)MPAD * D_IN];   // x split hi
__device__ __nv_bfloat16 g_xl[(size_t)MPAD * D_IN];   // x split lo
__device__ __nv_bfloat16 g_ah[(size_t)MPAD * D_HID];  // activation split hi
__device__ __nv_bfloat16 g_al[(size_t)MPAD * D_HID];  // activation split lo
// weights, transposed [N][K], split hi/lo
__device__ __nv_bfloat16 g_w1h[D_IN * D_HID],  g_w1l[D_IN * D_HID];
__device__ __nv_bfloat16 g_w2h[D_HID * D_HID], g_w2l[D_HID * D_HID];
__device__ __nv_bfloat16 g_w3h[D_HID * D_HID], g_w3l[D_HID * D_HID];
__device__ __nv_bfloat16 g_w4h[D_HID * D_OUT], g_w4l[D_HID * D_OUT];
__device__ float g_pool[G * D_OUT];
__device__ int   g_gcnt[G];
__device__ int   g_goff[G + 1];

// ---------------- graph preprocessing ----------------
__global__ void init_kernel() {
    int i = blockIdx.x * blockDim.x + threadIdx.x;
    if (i < N_NODES) g_deg[i] = 1;       // self loop
    if (i < G) g_gcnt[i] = 0;
}

__global__ void hist_kernel(const int* __restrict__ dst,
                            const int* __restrict__ batch) {
    int e = blockIdx.x * blockDim.x + threadIdx.x;
    if (e < N_EDGES) atomicAdd(&g_deg[dst[e]], 1);
    if (e < N_NODES) atomicAdd(&g_gcnt[batch[e]], 1);
}

// 3-phase exclusive scan of g_deg -> g_rowptr
__global__ void scan_part_kernel() {
    __shared__ int sdata[256];
    int t = threadIdx.x;
    int i = blockIdx.x * 256 + t;
    int v = (i < N_NODES) ? g_deg[i] : 0;
    sdata[t] = v;
    __syncthreads();
#pragma unroll
    for (int off = 1; off < 256; off <<= 1) {
        int tmp = (t >= off) ? sdata[t - off] : 0;
        __syncthreads();
        sdata[t] += tmp;
        __syncthreads();
    }
    if (i < N_NODES) g_rowptr[i] = sdata[t] - v;   // local exclusive
    if (t == 255) g_part[blockIdx.x] = sdata[255];
}

// parallel mid scan: threads 0-63 scan g_part (40 padded), 64-127 scan g_gcnt (64)
__global__ void scan_mid_kernel() {
    __shared__ int sa[64], sb[64];
    int t = threadIdx.x;
    int v0 = 0;
    if (t < 64) { v0 = (t < SCAN_BLKS) ? g_part[t] : 0; sa[t] = v0; }
    else        { v0 = g_gcnt[t - 64]; sb[t - 64] = v0; }
    __syncthreads();
#pragma unroll
    for (int off = 1; off < 64; off <<= 1) {
        int v = 0;
        if (t < 64) { if (t >= off) v = sa[t - off]; }
        else        { if ((t - 64) >= off) v = sb[t - 64 - off]; }
        __syncthreads();
        if (t < 64) sa[t] += v; else sb[t - 64] += v;
        __syncthreads();
    }
    if (t < SCAN_BLKS) g_poff[t] = sa[t] - v0;                 // exclusive
    if (t >= 64) {
        g_goff[t - 64] = sb[t - 64] - v0;                      // exclusive
        if (t == 127) g_goff[G] = sb[63];
    }
}

__global__ void scan_add_kernel() {
    int t = threadIdx.x;
    int i = blockIdx.x * 256 + t;
    if (i >= N_NODES) return;
    int excl = g_rowptr[i] + g_poff[blockIdx.x];
    g_rowptr[i] = excl;
    g_cursor[i] = excl;
    g_dis[i] = rsqrtf((float)g_deg[i]);
    if (i == 0) g_rowptr[N_NODES] = N_TOT;   // total is a known constant
}

__global__ void fill_csr_kernel(const int* __restrict__ src,
                                const int* __restrict__ dst) {
    int e = blockIdx.x * blockDim.x + threadIdx.x;
    if (e >= N_TOT) return;
    int s, d;
    if (e < N_EDGES) { s = src[e]; d = dst[e]; }
    else             { s = d = e - N_EDGES; }
    int pos = atomicAdd(&g_cursor[d], 1);
    g_col[pos] = s;
    g_val[pos] = g_dis[s] * g_dis[d];
}

// ---------------- bf16 split conversions ----------------
__global__ void wconv_kernel(const float* __restrict__ W, int K, int N, int layer) {
    __nv_bfloat16 *Wh, *Wl;
    switch (layer) {
        case 1: Wh = g_w1h; Wl = g_w1l; break;
        case 2: Wh = g_w2h; Wl = g_w2l; break;
        case 3: Wh = g_w3h; Wl = g_w3l; break;
        default: Wh = g_w4h; Wl = g_w4l; break;
    }
    int idx = blockIdx.x * blockDim.x + threadIdx.x;
    if (idx >= K * N) return;
    int k = idx / N, n = idx - k * N;
    float v = W[idx];
    __nv_bfloat16 h = __float2bfloat16(v);
    __nv_bfloat16 l = __float2bfloat16(v - __bfloat162float(h));
    Wh[(size_t)n * K + k] = h;
    Wl[(size_t)n * K + k] = l;
}

__global__ void xconv_kernel(const float* __restrict__ x) {
    int idx = blockIdx.x * blockDim.x + threadIdx.x;
    if (idx >= N_NODES * D_IN) return;
    float v = x[idx];
    __nv_bfloat16 h = __float2bfloat16(v);
    g_xh[idx] = h;
    g_xl[idx] = __float2bfloat16(v - __bfloat162float(h));
}

// ---------------- tensor-core GEMM: g_h1[M,N] = A[M,K] @ Bt[N,K]^T ----------------
// (R4/R7 structure — the fastest measured variant)
#define GBK      32
#define ASTRIDE  40                  // bf16 per smem row (32 + 8 pad) -> 20 words
#define TILE_W   2560                // words per tile (128 * 20)
#define STAGE_W  10240               // words per stage (4 tiles)
#define SMEM_BYTES (2 * STAGE_W * 4) // 81920

__device__ __forceinline__ void cp16(uint32_t dst, const void* src) {
    asm volatile("cp.async.ca.shared.global [%0], [%1], 16;" :: "r"(dst), "l"(src));
}

__device__ __forceinline__ void mma_bf16(float c[4], const uint32_t a[4],
                                         uint32_t b0, uint32_t b1) {
    asm volatile(
        "mma.sync.aligned.m16n8k16.row.col.f32.bf16.bf16.f32 "
        "{%0,%1,%2,%3}, {%4,%5,%6,%7}, {%8,%9}, {%0,%1,%2,%3};"
        : "+f"(c[0]), "+f"(c[1]), "+f"(c[2]), "+f"(c[3])
        : "r"(a[0]), "r"(a[1]), "r"(a[2]), "r"(a[3]), "r"(b0), "r"(b1));
}

__global__ __launch_bounds__(256, 2) void mma_gemm_kernel(int asel, int layer,
                                                          int K, int N) {
    extern __shared__ __nv_bfloat16 smem[];
    const __nv_bfloat16 *Ah, *Al, *Bh, *Bl;
    if (asel == 0) { Ah = g_xh; Al = g_xl; } else { Ah = g_ah; Al = g_al; }
    switch (layer) {
        case 1: Bh = g_w1h; Bl = g_w1l; break;
        case 2: Bh = g_w2h; Bl = g_w2l; break;
        case 3: Bh = g_w3h; Bl = g_w3l; break;
        default: Bh = g_w4h; Bl = g_w4l; break;
    }
    int tid = threadIdx.x;
    int brow = blockIdx.y * 128;
    int bcol = blockIdx.x * 128;

    int lrow = tid >> 1;
    int lhalf = tid & 1;
    const __nv_bfloat16* agh = Ah + (size_t)(brow + lrow) * K + lhalf * 16;
    const __nv_bfloat16* agl = Al + (size_t)(brow + lrow) * K + lhalf * 16;
    const __nv_bfloat16* bgh = Bh + (size_t)(bcol + lrow) * K + lhalf * 16;
    const __nv_bfloat16* bgl = Bl + (size_t)(bcol + lrow) * K + lhalf * 16;
    uint32_t sbase = (uint32_t)__cvta_generic_to_shared(smem);
    uint32_t sdst = sbase + (uint32_t)(lrow * ASTRIDE + lhalf * 16) * 2;

    int warp = tid >> 5, lane = tid & 31;
    int wm = warp >> 2, wn = warp & 3;       // 2 x 4 warp grid
    int group = lane >> 2, quad = lane & 3;

    float acc[4][4][4];
#pragma unroll
    for (int i = 0; i < 4; i++)
#pragma unroll
        for (int j = 0; j < 4; j++)
#pragma unroll
            for (int v = 0; v < 4; v++) acc[i][j][v] = 0.f;

    int NK = K / GBK;
    {
        const __nv_bfloat16* s4[4] = { agh, agl, bgh, bgl };
#pragma unroll
        for (int j = 0; j < 4; j++) {
            uint32_t d = sdst + j * (TILE_W * 4);
            cp16(d, s4[j]);
            cp16(d + 16, (const char*)s4[j] + 16);
        }
        asm volatile("cp.async.commit_group;");
    }

    for (int it = 0; it < NK; it++) {
        if (it + 1 < NK) {
            int k0 = (it + 1) * GBK;
            uint32_t stg = ((it + 1) & 1) * (STAGE_W * 4);
            const __nv_bfloat16* s4[4] = { agh + k0, agl + k0, bgh + k0, bgl + k0 };
#pragma unroll
            for (int j = 0; j < 4; j++) {
                uint32_t d = sdst + stg + j * (TILE_W * 4);
                cp16(d, s4[j]);
                cp16(d + 16, (const char*)s4[j] + 16);
            }
        }
        asm volatile("cp.async.commit_group;");
        asm volatile("cp.async.wait_group 1;");
        __syncthreads();

        const uint32_t* sw = (const uint32_t*)smem + (it & 1) * STAGE_W;
        const uint32_t* sAh32 = sw;
        const uint32_t* sAl32 = sw + TILE_W;
        const uint32_t* sBh32 = sw + 2 * TILE_W;
        const uint32_t* sBl32 = sw + 3 * TILE_W;

#pragma unroll
        for (int kk = 0; kk < 2; kk++) {
            int kb = kk * 8;
            uint32_t ah[4][4], al[4][4];
#pragma unroll
            for (int im = 0; im < 4; im++) {
                int r = wm * 64 + im * 16 + group;
                int i0 = r * 20 + kb + quad;
                int i1 = (r + 8) * 20 + kb + quad;
                ah[im][0] = sAh32[i0];     ah[im][1] = sAh32[i1];
                ah[im][2] = sAh32[i0 + 4]; ah[im][3] = sAh32[i1 + 4];
                al[im][0] = sAl32[i0];     al[im][1] = sAl32[i1];
                al[im][2] = sAl32[i0 + 4]; al[im][3] = sAl32[i1 + 4];
            }
#pragma unroll
            for (int in_ = 0; in_ < 4; in_++) {
                int n = wn * 32 + in_ * 8 + group;
                int j0 = n * 20 + kb + quad;
                uint32_t bh0 = sBh32[j0], bh1 = sBh32[j0 + 4];
                uint32_t bl0 = sBl32[j0], bl1 = sBl32[j0 + 4];
#pragma unroll
                for (int im = 0; im < 4; im++) {
                    mma_bf16(acc[im][in_], ah[im], bh0, bh1);
                    mma_bf16(acc[im][in_], ah[im], bl0, bl1);
                    mma_bf16(acc[im][in_], al[im], bh0, bh1);
                }
            }
        }
        __syncthreads();
    }

#pragma unroll
    for (int im = 0; im < 4; im++) {
        int r = brow + wm * 64 + im * 16 + group;
#pragma unroll
        for (int in_ = 0; in_ < 4; in_++) {
            int c = bcol + wn * 32 + in_ * 8 + quad * 2;
            float2 lo = make_float2(acc[im][in_][0], acc[im][in_][1]);
            float2 hi = make_float2(acc[im][in_][2], acc[im][in_][3]);
            *(float2*)(g_h1 + (size_t)r * N + c) = lo;
            *(float2*)(g_h1 + (size_t)(r + 8) * N + c) = hi;
        }
    }
}

// ---------------- aggregation (layers 1-3): bias+relu, write bf16 hi/lo split ----
__global__ void aggregate_bf_kernel(const float* __restrict__ bias) {
    int i = blockIdx.x;
    int t = threadIdx.x;     // 128 threads (D_HID/4)
    int s = g_rowptr[i], e = g_rowptr[i + 1];
    float4 acc = make_float4(0.f, 0.f, 0.f, 0.f);
    const float4* hin4 = (const float4*)g_h1;
    for (int p = s; p < e; p++) {
        int c = g_col[p];
        float v = g_val[p];
        float4 x = hin4[(size_t)c * 128 + t];
        acc.x += v * x.x; acc.y += v * x.y; acc.z += v * x.z; acc.w += v * x.w;
    }
    float4 b = ((const float4*)bias)[t];
    acc.x = fmaxf(acc.x + b.x, 0.f); acc.y = fmaxf(acc.y + b.y, 0.f);
    acc.z = fmaxf(acc.z + b.z, 0.f); acc.w = fmaxf(acc.w + b.w, 0.f);
    __nv_bfloat16 hx = __float2bfloat16(acc.x), hy = __float2bfloat16(acc.y);
    __nv_bfloat16 hz = __float2bfloat16(acc.z), hw = __float2bfloat16(acc.w);
    __nv_bfloat16 lx = __float2bfloat16(acc.x - __bfloat162float(hx));
    __nv_bfloat16 ly = __float2bfloat16(acc.y - __bfloat162float(hy));
    __nv_bfloat16 lz = __float2bfloat16(acc.z - __bfloat162float(hz));
    __nv_bfloat16 lw = __float2bfloat16(acc.w - __bfloat162float(hw));
    __nv_bfloat162* oh = (__nv_bfloat162*)(g_ah + (size_t)i * D_HID);
    __nv_bfloat162* ol = (__nv_bfloat162*)(g_al + (size_t)i * D_HID);
    __nv_bfloat162 p0; p0.x = hx; p0.y = hy;
    __nv_bfloat162 p1; p1.x = hz; p1.y = hw;
    __nv_bfloat162 q0; q0.x = lx; q0.y = ly;
    __nv_bfloat162 q1; q1.x = lz; q1.y = lw;
    oh[t * 2] = p0; oh[t * 2 + 1] = p1;
    ol[t * 2] = q0; ol[t * 2 + 1] = q1;
}

// ---------------- aggregation (layer 4): bias, fp32 out, 2 nodes/block ----------
__global__ void aggregate_f32_kernel(const float* __restrict__ bias) {
    int i = blockIdx.x * 2 + (threadIdx.x >> 6);
    int t = threadIdx.x & 63;     // 64 threads per node (D_OUT/4)
    if (i >= N_NODES) return;
    int s = g_rowptr[i], e = g_rowptr[i + 1];
    float4 acc = make_float4(0.f, 0.f, 0.f, 0.f);
    const float4* hin4 = (const float4*)g_h1;
    for (int p = s; p < e; p++) {
        int c = g_col[p];
        float v = g_val[p];
        float4 x = hin4[(size_t)c * 64 + t];
        acc.x += v * x.x; acc.y += v * x.y; acc.z += v * x.z; acc.w += v * x.w;
    }
    float4 b = ((const float4*)bias)[t];
    acc.x += b.x; acc.y += b.y; acc.z += b.z; acc.w += b.w;
    ((float4*)g_h2)[(size_t)i * 64 + t] = acc;
}

// ---------------- pooling + L2 normalize (reads g_h2) ----------------
__global__ void pool_kernel() {
    __shared__ float red[256];
    int g = blockIdx.x, t = threadIdx.x;
    int s = g_goff[g], e = g_goff[g + 1];
    float acc = 0.f;
    for (int n = s; n < e; n++) acc += g_h2[(size_t)n * D_OUT + t];
    float cnt = (float)(e - s);
    float mean = acc / fmaxf(cnt, 1.f);
    red[t] = mean * mean;
    __syncthreads();
    for (int off = 128; off > 0; off >>= 1) {
        if (t < off) red[t] += red[t + off];
        __syncthreads();
    }
    float nrm = sqrtf(red[0]);
    g_pool[g * D_OUT + t] = mean / fmaxf(nrm, 1e-12f);
}

// ---------------- classifier MLP head ----------------
__global__ void mlp_kernel(const float* __restrict__ vec,
                           const float* __restrict__ cW1, const float* __restrict__ cb1,
                           const float* __restrict__ cW2, const float* __restrict__ cb2,
                           const float* __restrict__ cW3, const float* __restrict__ cb3,
                           float* __restrict__ out) {
    __shared__ float comb[512];
    __shared__ float z1[256];
    __shared__ float z2[64];
    int g = blockIdx.x, t = threadIdx.x;   // 256 threads
    comb[t] = g_pool[g * 256 + t];
    comb[256 + t] = vec[g * 256 + t];
    __syncthreads();
    float s1 = cb1[t];
    for (int k = 0; k < 512; k++) s1 += comb[k] * cW1[k * 256 + t];
    z1[t] = fmaxf(s1, 0.f);
    __syncthreads();
    if (t < 64) {
        float s2 = cb2[t];
        for (int k = 0; k < 256; k++) s2 += z1[k] * cW2[k * 64 + t];
        z2[t] = fmaxf(s2, 0.f);
    }
    __syncthreads();
    if (t == 0) {
        float s3 = cb3[0];
        for (int k = 0; k < 64; k++) s3 += z2[k] * cW3[k];
        out[g] = 1.f / (1.f + expf(-s3));
    }
}

// ---------------- launch ----------------
extern "C" void kernel_launch(void* const* d_in, const int* in_sizes, int n_in,
                              void* d_out, int out_size) {
    const float* x    = (const float*)d_in[0];
    const int*   ei   = (const int*)d_in[1];   // [2, E] int32
    const int*   bat  = (const int*)d_in[2];
    const float* vec  = (const float*)d_in[3];
    const float* W1 = (const float*)d_in[4],  *b1 = (const float*)d_in[5];
    const float* W2 = (const float*)d_in[6],  *b2 = (const float*)d_in[7];
    const float* W3 = (const float*)d_in[8],  *b3 = (const float*)d_in[9];
    const float* W4 = (const float*)d_in[10], *b4 = (const float*)d_in[11];
    const float* cW1 = (const float*)d_in[12], *cb1 = (const float*)d_in[13];
    const float* cW2 = (const float*)d_in[14], *cb2 = (const float*)d_in[15];
    const float* cW3 = (const float*)d_in[16], *cb3 = (const float*)d_in[17];
    float* out = (float*)d_out;

    const int* src = ei;
    const int* dst = ei + N_EDGES;

    cudaFuncSetAttribute(mma_gemm_kernel,
                         cudaFuncAttributeMaxDynamicSharedMemorySize, SMEM_BYTES);

    // side stream + events for capture-fork (created once; no device allocation)
    static cudaStream_t s_side = nullptr;
    static cudaEvent_t ev_fork = nullptr, ev_join = nullptr;
    if (s_side == nullptr) {
        cudaStreamCreateWithFlags(&s_side, cudaStreamNonBlocking);
        cudaEventCreateWithFlags(&ev_fork, cudaEventDisableTiming);
        cudaEventCreateWithFlags(&ev_join, cudaEventDisableTiming);
    }

    // fork: side stream runs CSR preprocessing + wconv2-4, overlapping GEMM1 path
    cudaEventRecord(ev_fork, 0);
    cudaStreamWaitEvent(s_side, ev_fork, 0);

    init_kernel<<<(N_NODES + 255) / 256, 256, 0, s_side>>>();
    hist_kernel<<<(N_EDGES + 255) / 256, 256, 0, s_side>>>(dst, bat);
    scan_part_kernel<<<SCAN_BLKS, 256, 0, s_side>>>();
    scan_mid_kernel<<<1, 128, 0, s_side>>>();
    scan_add_kernel<<<SCAN_BLKS, 256, 0, s_side>>>();
    fill_csr_kernel<<<(N_TOT + 255) / 256, 256, 0, s_side>>>(src, dst);
    wconv_kernel<<<(D_HID * D_HID + 255) / 256, 256, 0, s_side>>>(W2, D_HID, D_HID, 2);
    wconv_kernel<<<(D_HID * D_HID + 255) / 256, 256, 0, s_side>>>(W3, D_HID, D_HID, 3);
    wconv_kernel<<<(D_HID * D_OUT + 255) / 256, 256, 0, s_side>>>(W4, D_HID, D_OUT, 4);
    cudaEventRecord(ev_join, s_side);

    // main stream: conversions for layer 1 + GEMM1
    xconv_kernel<<<(N_NODES * D_IN + 255) / 256, 256>>>(x);
    wconv_kernel<<<(D_IN * D_HID + 255) / 256, 256>>>(W1, D_IN, D_HID, 1);

    dim3 blk(256);
    int gy = MPAD / 128;   // 79
    mma_gemm_kernel<<<dim3(D_HID / 128, gy), blk, SMEM_BYTES>>>(0, 1, D_IN, D_HID);

    // join: aggregate needs CSR (side) + GEMM1 output (main)
    cudaStreamWaitEvent(0, ev_join, 0);

    aggregate_bf_kernel<<<N_NODES, 128>>>(b1);
    // layer 2
    mma_gemm_kernel<<<dim3(D_HID / 128, gy), blk, SMEM_BYTES>>>(1, 2, D_HID, D_HID);
    aggregate_bf_kernel<<<N_NODES, 128>>>(b2);
    // layer 3
    mma_gemm_kernel<<<dim3(D_HID / 128, gy), blk, SMEM_BYTES>>>(1, 3, D_HID, D_HID);
    aggregate_bf_kernel<<<N_NODES, 128>>>(b3);
    // layer 4
    mma_gemm_kernel<<<dim3(D_OUT / 128, gy), blk, SMEM_BYTES>>>(1, 4, D_HID, D_OUT);
    aggregate_f32_kernel<<<(N_NODES + 1) / 2, 128>>>(b4);

    // pooling + normalize + head
    pool_kernel<<<G, 256>>>();
    mlp_kernel<<<G, 256>>>(vec, cW1, cb1, cW2, cb2, cW3, cb3, out);
}

// round 10
// speedup vs baseline: 1.5596x; 1.2293x over previous
#include <cuda_runtime.h>
#include <cuda_bf16.h>
#include <math.h>
#include <stdint.h>

#define N_NODES 10000
#define MPAD    10112           // 79 * 128 (padded row count, no M guards needed)
#define N_EDGES 160000
#define N_TOT   (N_EDGES + N_NODES)
#define G       64
#define D_IN    1280
#define D_HID   512
#define D_OUT   256
#define SCAN_BLKS 40            // 40 * 256 = 10240 >= N_NODES

// ---------------- scratch (static device globals; no allocation) ----------------
__device__ int   g_deg[N_NODES];
__device__ float g_dis[N_NODES];
__device__ int   g_rowptr[N_NODES + 1];
__device__ int   g_cursor[N_NODES];
__device__ int   g_part[SCAN_BLKS];
__device__ int   g_poff[SCAN_BLKS];
__device__ int   g_col[N_TOT];
__device__ float g_val[N_TOT];
__device__ float g_h1[(size_t)MPAD * D_HID];     // GEMM output (fp32, pre-aggregation)
__device__ float g_h2[(size_t)MPAD * D_HID];     // final-layer aggregate output (fp32)
__device__ __nv_bfloat16 g_xh[(size_t)MPAD * D_IN];   // x as bf16
__device__ __nv_bfloat16 g_ah[(size_t)MPAD * D_HID];  // activations as bf16
// weights, transposed [N][K], split hi/lo (weights keep 2-term split)
__device__ __nv_bfloat16 g_w1h[D_IN * D_HID],  g_w1l[D_IN * D_HID];
__device__ __nv_bfloat16 g_w2h[D_HID * D_HID], g_w2l[D_HID * D_HID];
__device__ __nv_bfloat16 g_w3h[D_HID * D_HID], g_w3l[D_HID * D_HID];
__device__ __nv_bfloat16 g_w4h[D_HID * D_OUT], g_w4l[D_HID * D_OUT];
__device__ float g_pool[G * D_OUT];
__device__ int   g_gcnt[G];
__device__ int   g_goff[G + 1];

// ---------------- graph preprocessing ----------------
__global__ void init_kernel() {
    int i = blockIdx.x * blockDim.x + threadIdx.x;
    if (i < N_NODES) g_deg[i] = 1;       // self loop
    if (i < G) g_gcnt[i] = 0;
}

__global__ void hist_kernel(const int* __restrict__ dst,
                            const int* __restrict__ batch) {
    int e = blockIdx.x * blockDim.x + threadIdx.x;
    if (e < N_EDGES) atomicAdd(&g_deg[dst[e]], 1);
    if (e < N_NODES) atomicAdd(&g_gcnt[batch[e]], 1);
}

// 3-phase exclusive scan of g_deg -> g_rowptr
__global__ void scan_part_kernel() {
    __shared__ int sdata[256];
    int t = threadIdx.x;
    int i = blockIdx.x * 256 + t;
    int v = (i < N_NODES) ? g_deg[i] : 0;
    sdata[t] = v;
    __syncthreads();
#pragma unroll
    for (int off = 1; off < 256; off <<= 1) {
        int tmp = (t >= off) ? sdata[t - off] : 0;
        __syncthreads();
        sdata[t] += tmp;
        __syncthreads();
    }
    if (i < N_NODES) g_rowptr[i] = sdata[t] - v;   // local exclusive
    if (t == 255) g_part[blockIdx.x] = sdata[255];
}

// parallel mid scan: threads 0-63 scan g_part (40 padded), 64-127 scan g_gcnt (64)
__global__ void scan_mid_kernel() {
    __shared__ int sa[64], sb[64];
    int t = threadIdx.x;
    int v0 = 0;
    if (t < 64) { v0 = (t < SCAN_BLKS) ? g_part[t] : 0; sa[t] = v0; }
    else        { v0 = g_gcnt[t - 64]; sb[t - 64] = v0; }
    __syncthreads();
#pragma unroll
    for (int off = 1; off < 64; off <<= 1) {
        int v = 0;
        if (t < 64) { if (t >= off) v = sa[t - off]; }
        else        { if ((t - 64) >= off) v = sb[t - 64 - off]; }
        __syncthreads();
        if (t < 64) sa[t] += v; else sb[t - 64] += v;
        __syncthreads();
    }
    if (t < SCAN_BLKS) g_poff[t] = sa[t] - v0;                 // exclusive
    if (t >= 64) {
        g_goff[t - 64] = sb[t - 64] - v0;                      // exclusive
        if (t == 127) g_goff[G] = sb[63];
    }
}

__global__ void scan_add_kernel() {
    int t = threadIdx.x;
    int i = blockIdx.x * 256 + t;
    if (i >= N_NODES) return;
    int excl = g_rowptr[i] + g_poff[blockIdx.x];
    g_rowptr[i] = excl;
    g_cursor[i] = excl;
    g_dis[i] = rsqrtf((float)g_deg[i]);
    if (i == 0) g_rowptr[N_NODES] = N_TOT;   // total is a known constant
}

__global__ void fill_csr_kernel(const int* __restrict__ src,
                                const int* __restrict__ dst) {
    int e = blockIdx.x * blockDim.x + threadIdx.x;
    if (e >= N_TOT) return;
    int s, d;
    if (e < N_EDGES) { s = src[e]; d = dst[e]; }
    else             { s = d = e - N_EDGES; }
    int pos = atomicAdd(&g_cursor[d], 1);
    g_col[pos] = s;
    g_val[pos] = g_dis[s] * g_dis[d];
}

// ---------------- conversions ----------------
__global__ void wconv_kernel(const float* __restrict__ W, int K, int N, int layer) {
    __nv_bfloat16 *Wh, *Wl;
    switch (layer) {
        case 1: Wh = g_w1h; Wl = g_w1l; break;
        case 2: Wh = g_w2h; Wl = g_w2l; break;
        case 3: Wh = g_w3h; Wl = g_w3l; break;
        default: Wh = g_w4h; Wl = g_w4l; break;
    }
    int idx = blockIdx.x * blockDim.x + threadIdx.x;
    if (idx >= K * N) return;
    int k = idx / N, n = idx - k * N;
    float v = W[idx];
    __nv_bfloat16 h = __float2bfloat16(v);
    __nv_bfloat16 l = __float2bfloat16(v - __bfloat162float(h));
    Wh[(size_t)n * K + k] = h;
    Wl[(size_t)n * K + k] = l;
}

__global__ void xconv_kernel(const float* __restrict__ x) {
    int idx = blockIdx.x * blockDim.x + threadIdx.x;
    if (idx >= N_NODES * D_IN) return;
    g_xh[idx] = __float2bfloat16(x[idx]);
}

// ---------------- tensor-core GEMM: g_h1[M,N] = A[M,K] @ (Bh+Bl)[N,K]^T ----------
// 2-term scheme: A single bf16, B split hi/lo. fp32 accum.
// Block 128x128x32, 8 warps (2x4), warp tile 64x32. 32 MMAs/warp/k16.
#define GBK      32
#define ASTRIDE  40                  // bf16 per smem row (32 + 8 pad) -> 20 words
#define TILE_W   2560                // words per tile (128 * 20)
#define STAGE_W  7680                // words per stage (3 tiles: A, Bh, Bl)
#define SMEM_BYTES (2 * STAGE_W * 4) // 61440

__device__ __forceinline__ void cp16(uint32_t dst, const void* src) {
    asm volatile("cp.async.ca.shared.global [%0], [%1], 16;" :: "r"(dst), "l"(src));
}

__device__ __forceinline__ void mma_bf16(float c[4], const uint32_t a[4],
                                         uint32_t b0, uint32_t b1) {
    asm volatile(
        "mma.sync.aligned.m16n8k16.row.col.f32.bf16.bf16.f32 "
        "{%0,%1,%2,%3}, {%4,%5,%6,%7}, {%8,%9}, {%0,%1,%2,%3};"
        : "+f"(c[0]), "+f"(c[1]), "+f"(c[2]), "+f"(c[3])
        : "r"(a[0]), "r"(a[1]), "r"(a[2]), "r"(a[3]), "r"(b0), "r"(b1));
}

__global__ __launch_bounds__(256, 2) void mma_gemm_kernel(int asel, int layer,
                                                          int K, int N) {
    extern __shared__ __nv_bfloat16 smem[];
    const __nv_bfloat16 *A, *Bh, *Bl;
    A = (asel == 0) ? g_xh : g_ah;
    switch (layer) {
        case 1: Bh = g_w1h; Bl = g_w1l; break;
        case 2: Bh = g_w2h; Bl = g_w2l; break;
        case 3: Bh = g_w3h; Bl = g_w3l; break;
        default: Bh = g_w4h; Bl = g_w4l; break;
    }
    int tid = threadIdx.x;
    int brow = blockIdx.y * 128;
    int bcol = blockIdx.x * 128;

    int lrow = tid >> 1;
    int lhalf = tid & 1;
    const __nv_bfloat16* ag  = A  + (size_t)(brow + lrow) * K + lhalf * 16;
    const __nv_bfloat16* bgh = Bh + (size_t)(bcol + lrow) * K + lhalf * 16;
    const __nv_bfloat16* bgl = Bl + (size_t)(bcol + lrow) * K + lhalf * 16;
    uint32_t sbase = (uint32_t)__cvta_generic_to_shared(smem);
    uint32_t sdst = sbase + (uint32_t)(lrow * ASTRIDE + lhalf * 16) * 2;

    int warp = tid >> 5, lane = tid & 31;
    int wm = warp >> 2, wn = warp & 3;       // 2 x 4 warp grid
    int group = lane >> 2, quad = lane & 3;

    float acc[4][4][4];
#pragma unroll
    for (int i = 0; i < 4; i++)
#pragma unroll
        for (int j = 0; j < 4; j++)
#pragma unroll
            for (int v = 0; v < 4; v++) acc[i][j][v] = 0.f;

    int NK = K / GBK;
    {
        const __nv_bfloat16* s3[3] = { ag, bgh, bgl };
#pragma unroll
        for (int j = 0; j < 3; j++) {
            uint32_t d = sdst + j * (TILE_W * 4);
            cp16(d, s3[j]);
            cp16(d + 16, (const char*)s3[j] + 16);
        }
        asm volatile("cp.async.commit_group;");
    }

    for (int it = 0; it < NK; it++) {
        if (it + 1 < NK) {
            int k0 = (it + 1) * GBK;
            uint32_t stg = ((it + 1) & 1) * (STAGE_W * 4);
            const __nv_bfloat16* s3[3] = { ag + k0, bgh + k0, bgl + k0 };
#pragma unroll
            for (int j = 0; j < 3; j++) {
                uint32_t d = sdst + stg + j * (TILE_W * 4);
                cp16(d, s3[j]);
                cp16(d + 16, (const char*)s3[j] + 16);
            }
        }
        asm volatile("cp.async.commit_group;");
        asm volatile("cp.async.wait_group 1;");
        __syncthreads();

        const uint32_t* sw = (const uint32_t*)smem + (it & 1) * STAGE_W;
        const uint32_t* sA32  = sw;
        const uint32_t* sBh32 = sw + TILE_W;
        const uint32_t* sBl32 = sw + 2 * TILE_W;

#pragma unroll
        for (int kk = 0; kk < 2; kk++) {
            int kb = kk * 8;
            uint32_t ah[4][4];
#pragma unroll
            for (int im = 0; im < 4; im++) {
                int r = wm * 64 + im * 16 + group;
                int i0 = r * 20 + kb + quad;
                int i1 = (r + 8) * 20 + kb + quad;
                ah[im][0] = sA32[i0];     ah[im][1] = sA32[i1];
                ah[im][2] = sA32[i0 + 4]; ah[im][3] = sA32[i1 + 4];
            }
#pragma unroll
            for (int in_ = 0; in_ < 4; in_++) {
                int n = wn * 32 + in_ * 8 + group;
                int j0 = n * 20 + kb + quad;
                uint32_t bh0 = sBh32[j0], bh1 = sBh32[j0 + 4];
                uint32_t bl0 = sBl32[j0], bl1 = sBl32[j0 + 4];
#pragma unroll
                for (int im = 0; im < 4; im++) {
                    mma_bf16(acc[im][in_], ah[im], bh0, bh1);
                    mma_bf16(acc[im][in_], ah[im], bl0, bl1);
                }
            }
        }
        __syncthreads();
    }

#pragma unroll
    for (int im = 0; im < 4; im++) {
        int r = brow + wm * 64 + im * 16 + group;
#pragma unroll
        for (int in_ = 0; in_ < 4; in_++) {
            int c = bcol + wn * 32 + in_ * 8 + quad * 2;
            float2 lo = make_float2(acc[im][in_][0], acc[im][in_][1]);
            float2 hi = make_float2(acc[im][in_][2], acc[im][in_][3]);
            *(float2*)(g_h1 + (size_t)r * N + c) = lo;
            *(float2*)(g_h1 + (size_t)(r + 8) * N + c) = hi;
        }
    }
}

// ---------------- aggregation (layers 1-3): bias+relu, write single bf16 ----------
__global__ void aggregate_bf_kernel(const float* __restrict__ bias) {
    int i = blockIdx.x;
    int t = threadIdx.x;     // 128 threads (D_HID/4)
    int s = g_rowptr[i], e = g_rowptr[i + 1];
    float4 acc = make_float4(0.f, 0.f, 0.f, 0.f);
    const float4* hin4 = (const float4*)g_h1;
    for (int p = s; p < e; p++) {
        int c = g_col[p];
        float v = g_val[p];
        float4 x = hin4[(size_t)c * 128 + t];
        acc.x += v * x.x; acc.y += v * x.y; acc.z += v * x.z; acc.w += v * x.w;
    }
    float4 b = ((const float4*)bias)[t];
    acc.x = fmaxf(acc.x + b.x, 0.f); acc.y = fmaxf(acc.y + b.y, 0.f);
    acc.z = fmaxf(acc.z + b.z, 0.f); acc.w = fmaxf(acc.w + b.w, 0.f);
    __nv_bfloat162 p0; p0.x = __float2bfloat16(acc.x); p0.y = __float2bfloat16(acc.y);
    __nv_bfloat162 p1; p1.x = __float2bfloat16(acc.z); p1.y = __float2bfloat16(acc.w);
    __nv_bfloat162* oh = (__nv_bfloat162*)(g_ah + (size_t)i * D_HID);
    oh[t * 2] = p0; oh[t * 2 + 1] = p1;
}

// ---------------- aggregation (layer 4): bias, fp32 out, 2 nodes/block ----------
__global__ void aggregate_f32_kernel(const float* __restrict__ bias) {
    int i = blockIdx.x * 2 + (threadIdx.x >> 6);
    int t = threadIdx.x & 63;     // 64 threads per node (D_OUT/4)
    if (i >= N_NODES) return;
    int s = g_rowptr[i], e = g_rowptr[i + 1];
    float4 acc = make_float4(0.f, 0.f, 0.f, 0.f);
    const float4* hin4 = (const float4*)g_h1;
    for (int p = s; p < e; p++) {
        int c = g_col[p];
        float v = g_val[p];
        float4 x = hin4[(size_t)c * 64 + t];
        acc.x += v * x.x; acc.y += v * x.y; acc.z += v * x.z; acc.w += v * x.w;
    }
    float4 b = ((const float4*)bias)[t];
    acc.x += b.x; acc.y += b.y; acc.z += b.z; acc.w += b.w;
    ((float4*)g_h2)[(size_t)i * 64 + t] = acc;
}

// ---------------- pooling + L2 normalize (reads g_h2) ----------------
__global__ void pool_kernel() {
    __shared__ float red[256];
    int g = blockIdx.x, t = threadIdx.x;
    int s = g_goff[g], e = g_goff[g + 1];
    float acc = 0.f;
    for (int n = s; n < e; n++) acc += g_h2[(size_t)n * D_OUT + t];
    float cnt = (float)(e - s);
    float mean = acc / fmaxf(cnt, 1.f);
    red[t] = mean * mean;
    __syncthreads();
    for (int off = 128; off > 0; off >>= 1) {
        if (t < off) red[t] += red[t + off];
        __syncthreads();
    }
    float nrm = sqrtf(red[0]);
    g_pool[g * D_OUT + t] = mean / fmaxf(nrm, 1e-12f);
}

// ---------------- classifier MLP head ----------------
__global__ void mlp_kernel(const float* __restrict__ vec,
                           const float* __restrict__ cW1, const float* __restrict__ cb1,
                           const float* __restrict__ cW2, const float* __restrict__ cb2,
                           const float* __restrict__ cW3, const float* __restrict__ cb3,
                           float* __restrict__ out) {
    __shared__ float comb[512];
    __shared__ float z1[256];
    __shared__ float z2[64];
    int g = blockIdx.x, t = threadIdx.x;   // 256 threads
    comb[t] = g_pool[g * 256 + t];
    comb[256 + t] = vec[g * 256 + t];
    __syncthreads();
    float s1 = cb1[t];
    for (int k = 0; k < 512; k++) s1 += comb[k] * cW1[k * 256 + t];
    z1[t] = fmaxf(s1, 0.f);
    __syncthreads();
    if (t < 64) {
        float s2 = cb2[t];
        for (int k = 0; k < 256; k++) s2 += z1[k] * cW2[k * 64 + t];
        z2[t] = fmaxf(s2, 0.f);
    }
    __syncthreads();
    if (t == 0) {
        float s3 = cb3[0];
        for (int k = 0; k < 64; k++) s3 += z2[k] * cW3[k];
        out[g] = 1.f / (1.f + expf(-s3));
    }
}

// ---------------- launch ----------------
extern "C" void kernel_launch(void* const* d_in, const int* in_sizes, int n_in,
                              void* d_out, int out_size) {
    const float* x    = (const float*)d_in[0];
    const int*   ei   = (const int*)d_in[1];   // [2, E] int32
    const int*   bat  = (const int*)d_in[2];
    const float* vec  = (const float*)d_in[3];
    const float* W1 = (const float*)d_in[4],  *b1 = (const float*)d_in[5];
    const float* W2 = (const float*)d_in[6],  *b2 = (const float*)d_in[7];
    const float* W3 = (const float*)d_in[8],  *b3 = (const float*)d_in[9];
    const float* W4 = (const float*)d_in[10], *b4 = (const float*)d_in[11];
    const float* cW1 = (const float*)d_in[12], *cb1 = (const float*)d_in[13];
    const float* cW2 = (const float*)d_in[14], *cb2 = (const float*)d_in[15];
    const float* cW3 = (const float*)d_in[16], *cb3 = (const float*)d_in[17];
    float* out = (float*)d_out;

    const int* src = ei;
    const int* dst = ei + N_EDGES;

    cudaFuncSetAttribute(mma_gemm_kernel,
                         cudaFuncAttributeMaxDynamicSharedMemorySize, SMEM_BYTES);

    // side stream + events for capture-fork (created once; no device allocation)
    static cudaStream_t s_side = nullptr;
    static cudaEvent_t ev_fork = nullptr, ev_join = nullptr;
    if (s_side == nullptr) {
        cudaStreamCreateWithFlags(&s_side, cudaStreamNonBlocking);
        cudaEventCreateWithFlags(&ev_fork, cudaEventDisableTiming);
        cudaEventCreateWithFlags(&ev_join, cudaEventDisableTiming);
    }

    // fork: side stream runs CSR preprocessing + wconv2-4, overlapping GEMM1 path
    cudaEventRecord(ev_fork, 0);
    cudaStreamWaitEvent(s_side, ev_fork, 0);

    init_kernel<<<(N_NODES + 255) / 256, 256, 0, s_side>>>();
    hist_kernel<<<(N_EDGES + 255) / 256, 256, 0, s_side>>>(dst, bat);
    scan_part_kernel<<<SCAN_BLKS, 256, 0, s_side>>>();
    scan_mid_kernel<<<1, 128, 0, s_side>>>();
    scan_add_kernel<<<SCAN_BLKS, 256, 0, s_side>>>();
    fill_csr_kernel<<<(N_TOT + 255) / 256, 256, 0, s_side>>>(src, dst);
    wconv_kernel<<<(D_HID * D_HID + 255) / 256, 256, 0, s_side>>>(W2, D_HID, D_HID, 2);
    wconv_kernel<<<(D_HID * D_HID + 255) / 256, 256, 0, s_side>>>(W3, D_HID, D_HID, 3);
    wconv_kernel<<<(D_HID * D_OUT + 255) / 256, 256, 0, s_side>>>(W4, D_HID, D_OUT, 4);
    cudaEventRecord(ev_join, s_side);

    // main stream: conversions for layer 1 + GEMM1
    xconv_kernel<<<(N_NODES * D_IN + 255) / 256, 256>>>(x);
    wconv_kernel<<<(D_IN * D_HID + 255) / 256, 256>>>(W1, D_IN, D_HID, 1);

    dim3 blk(256);
    int gy = MPAD / 128;   // 79
    mma_gemm_kernel<<<dim3(D_HID / 128, gy), blk, SMEM_BYTES>>>(0, 1, D_IN, D_HID);

    // join: aggregate needs CSR (side) + GEMM1 output (main)
    cudaStreamWaitEvent(0, ev_join, 0);

    aggregate_bf_kernel<<<N_NODES, 128>>>(b1);
    // layer 2
    mma_gemm_kernel<<<dim3(D_HID / 128, gy), blk, SMEM_BYTES>>>(1, 2, D_HID, D_HID);
    aggregate_bf_kernel<<<N_NODES, 128>>>(b2);
    // layer 3
    mma_gemm_kernel<<<dim3(D_HID / 128, gy), blk, SMEM_BYTES>>>(1, 3, D_HID, D_HID);
    aggregate_bf_kernel<<<N_NODES, 128>>>(b3);
    // layer 4
    mma_gemm_kernel<<<dim3(D_OUT / 128, gy), blk, SMEM_BYTES>>>(1, 4, D_HID, D_OUT);
    aggregate_f32_kernel<<<(N_NODES + 1) / 2, 128>>>(b4);

    // pooling + normalize + head
    pool_kernel<<<G, 256>>>();
    mlp_kernel<<<G, 256>>>(vec, cW1, cb1, cW2, cb2, cW3, cb3, out);
}

// round 11
// speedup vs baseline: 2.1175x; 1.3577x over previous
#include <cuda_runtime.h>
#include <cuda_fp16.h>
#include <math.h>
#include <stdint.h>

#define N_NODES 10000
#define MPAD    10112           // 79 * 128 (padded row count, no M guards needed)
#define N_EDGES 160000
#define N_TOT   (N_EDGES + N_NODES)
#define G       64
#define D_IN    1280
#define D_HID   512
#define D_OUT   256
#define SCAN_BLKS 40            // 40 * 256 = 10240 >= N_NODES

// ---------------- scratch (static device globals; no allocation) ----------------
__device__ int   g_deg[N_NODES];
__device__ float g_dis[N_NODES];
__device__ int   g_rowptr[N_NODES + 1];
__device__ int   g_cursor[N_NODES];
__device__ int   g_part[SCAN_BLKS];
__device__ int   g_poff[SCAN_BLKS];
__device__ int   g_col[N_TOT];
__device__ float g_val[N_TOT];
__device__ __half g_h1[(size_t)MPAD * D_HID];    // GEMM output (fp16, pre-aggregation)
__device__ float  g_h2[(size_t)MPAD * D_OUT];    // final-layer aggregate output (fp32)
__device__ __half g_x[(size_t)MPAD * D_IN];      // x as fp16
__device__ __half g_a[(size_t)MPAD * D_HID];     // activations as fp16
// weights, transposed [N][K], single fp16
__device__ __half g_w1[D_IN * D_HID];
__device__ __half g_w2[D_HID * D_HID];
__device__ __half g_w3[D_HID * D_HID];
__device__ __half g_w4[D_HID * D_OUT];
__device__ float g_pool[G * D_OUT];
__device__ int   g_gcnt[G];
__device__ int   g_goff[G + 1];

// ---------------- graph preprocessing ----------------
__global__ void init_kernel() {
    int i = blockIdx.x * blockDim.x + threadIdx.x;
    if (i < N_NODES) g_deg[i] = 1;       // self loop
    if (i < G) g_gcnt[i] = 0;
}

__global__ void hist_kernel(const int* __restrict__ dst,
                            const int* __restrict__ batch) {
    int e = blockIdx.x * blockDim.x + threadIdx.x;
    if (e < N_EDGES) atomicAdd(&g_deg[dst[e]], 1);
    if (e < N_NODES) atomicAdd(&g_gcnt[batch[e]], 1);
}

// 3-phase exclusive scan of g_deg -> g_rowptr
__global__ void scan_part_kernel() {
    __shared__ int sdata[256];
    int t = threadIdx.x;
    int i = blockIdx.x * 256 + t;
    int v = (i < N_NODES) ? g_deg[i] : 0;
    sdata[t] = v;
    __syncthreads();
#pragma unroll
    for (int off = 1; off < 256; off <<= 1) {
        int tmp = (t >= off) ? sdata[t - off] : 0;
        __syncthreads();
        sdata[t] += tmp;
        __syncthreads();
    }
    if (i < N_NODES) g_rowptr[i] = sdata[t] - v;   // local exclusive
    if (t == 255) g_part[blockIdx.x] = sdata[255];
}

// parallel mid scan: threads 0-63 scan g_part (40 padded), 64-127 scan g_gcnt (64)
__global__ void scan_mid_kernel() {
    __shared__ int sa[64], sb[64];
    int t = threadIdx.x;
    int v0 = 0;
    if (t < 64) { v0 = (t < SCAN_BLKS) ? g_part[t] : 0; sa[t] = v0; }
    else        { v0 = g_gcnt[t - 64]; sb[t - 64] = v0; }
    __syncthreads();
#pragma unroll
    for (int off = 1; off < 64; off <<= 1) {
        int v = 0;
        if (t < 64) { if (t >= off) v = sa[t - off]; }
        else        { if ((t - 64) >= off) v = sb[t - 64 - off]; }
        __syncthreads();
        if (t < 64) sa[t] += v; else sb[t - 64] += v;
        __syncthreads();
    }
    if (t < SCAN_BLKS) g_poff[t] = sa[t] - v0;                 // exclusive
    if (t >= 64) {
        g_goff[t - 64] = sb[t - 64] - v0;                      // exclusive
        if (t == 127) g_goff[G] = sb[63];
    }
}

__global__ void scan_add_kernel() {
    int t = threadIdx.x;
    int i = blockIdx.x * 256 + t;
    if (i >= N_NODES) return;
    int excl = g_rowptr[i] + g_poff[blockIdx.x];
    g_rowptr[i] = excl;
    g_cursor[i] = excl;
    g_dis[i] = rsqrtf((float)g_deg[i]);
    if (i == 0) g_rowptr[N_NODES] = N_TOT;   // total is a known constant
}

__global__ void fill_csr_kernel(const int* __restrict__ src,
                                const int* __restrict__ dst) {
    int e = blockIdx.x * blockDim.x + threadIdx.x;
    if (e >= N_TOT) return;
    int s, d;
    if (e < N_EDGES) { s = src[e]; d = dst[e]; }
    else             { s = d = e - N_EDGES; }
    int pos = atomicAdd(&g_cursor[d], 1);
    g_col[pos] = s;
    g_val[pos] = g_dis[s] * g_dis[d];
}

// ---------------- conversions ----------------
__global__ void wconv_kernel(const float* __restrict__ W, int K, int N, int layer) {
    __half* Wt;
    switch (layer) {
        case 1: Wt = g_w1; break;
        case 2: Wt = g_w2; break;
        case 3: Wt = g_w3; break;
        default: Wt = g_w4; break;
    }
    int idx = blockIdx.x * blockDim.x + threadIdx.x;
    if (idx >= K * N) return;
    int k = idx / N, n = idx - k * N;
    Wt[(size_t)n * K + k] = __float2half(W[idx]);
}

__global__ void xconv_kernel(const float* __restrict__ x) {
    int idx = blockIdx.x * blockDim.x + threadIdx.x;
    if (idx >= N_NODES * D_IN) return;
    g_x[idx] = __float2half(x[idx]);
}

// ---------------- tensor-core GEMM: g_h1[M,N] = A[M,K] @ Bt[N,K]^T ----------------
// single-term fp16, fp32 accum. Block 128x128x32, 8 warps (2x4), warp tile 64x32.
#define GBK      32
#define ASTRIDE  40                  // fp16 per smem row (32 + 8 pad) -> 20 words
#define TILE_W   2560                // words per tile (128 * 20)
#define STAGE_W  5120                // words per stage (2 tiles: A, B)
#define SMEM_BYTES (2 * STAGE_W * 4) // 40960

__device__ __forceinline__ void cp16(uint32_t dst, const void* src) {
    asm volatile("cp.async.ca.shared.global [%0], [%1], 16;" :: "r"(dst), "l"(src));
}

__device__ __forceinline__ void mma_f16(float c[4], const uint32_t a[4],
                                        uint32_t b0, uint32_t b1) {
    asm volatile(
        "mma.sync.aligned.m16n8k16.row.col.f32.f16.f16.f32 "
        "{%0,%1,%2,%3}, {%4,%5,%6,%7}, {%8,%9}, {%0,%1,%2,%3};"
        : "+f"(c[0]), "+f"(c[1]), "+f"(c[2]), "+f"(c[3])
        : "r"(a[0]), "r"(a[1]), "r"(a[2]), "r"(a[3]), "r"(b0), "r"(b1));
}

__global__ __launch_bounds__(256, 2) void mma_gemm_kernel(int asel, int layer,
                                                          int K, int N) {
    extern __shared__ __half smem[];
    const __half *A, *B;
    A = (asel == 0) ? g_x : g_a;
    switch (layer) {
        case 1: B = g_w1; break;
        case 2: B = g_w2; break;
        case 3: B = g_w3; break;
        default: B = g_w4; break;
    }
    int tid = threadIdx.x;
    int brow = blockIdx.y * 128;
    int bcol = blockIdx.x * 128;

    int lrow = tid >> 1;
    int lhalf = tid & 1;
    const __half* ag = A + (size_t)(brow + lrow) * K + lhalf * 16;
    const __half* bg = B + (size_t)(bcol + lrow) * K + lhalf * 16;
    uint32_t sbase = (uint32_t)__cvta_generic_to_shared(smem);
    uint32_t sdst = sbase + (uint32_t)(lrow * ASTRIDE + lhalf * 16) * 2;

    int warp = tid >> 5, lane = tid & 31;
    int wm = warp >> 2, wn = warp & 3;       // 2 x 4 warp grid
    int group = lane >> 2, quad = lane & 3;

    float acc[4][4][4];
#pragma unroll
    for (int i = 0; i < 4; i++)
#pragma unroll
        for (int j = 0; j < 4; j++)
#pragma unroll
            for (int v = 0; v < 4; v++) acc[i][j][v] = 0.f;

    int NK = K / GBK;
    {
        cp16(sdst, ag);
        cp16(sdst + 16, (const char*)ag + 16);
        cp16(sdst + TILE_W * 4, bg);
        cp16(sdst + TILE_W * 4 + 16, (const char*)bg + 16);
        asm volatile("cp.async.commit_group;");
    }

    for (int it = 0; it < NK; it++) {
        if (it + 1 < NK) {
            int k0 = (it + 1) * GBK;
            uint32_t stg = ((it + 1) & 1) * (STAGE_W * 4);
            cp16(sdst + stg, ag + k0);
            cp16(sdst + stg + 16, (const char*)(ag + k0) + 16);
            cp16(sdst + stg + TILE_W * 4, bg + k0);
            cp16(sdst + stg + TILE_W * 4 + 16, (const char*)(bg + k0) + 16);
        }
        asm volatile("cp.async.commit_group;");
        asm volatile("cp.async.wait_group 1;");
        __syncthreads();

        const uint32_t* sw = (const uint32_t*)smem + (it & 1) * STAGE_W;
        const uint32_t* sA32 = sw;
        const uint32_t* sB32 = sw + TILE_W;

#pragma unroll
        for (int kk = 0; kk < 2; kk++) {
            int kb = kk * 8;
            uint32_t ah[4][4];
#pragma unroll
            for (int im = 0; im < 4; im++) {
                int r = wm * 64 + im * 16 + group;
                int i0 = r * 20 + kb + quad;
                int i1 = (r + 8) * 20 + kb + quad;
                ah[im][0] = sA32[i0];     ah[im][1] = sA32[i1];
                ah[im][2] = sA32[i0 + 4]; ah[im][3] = sA32[i1 + 4];
            }
#pragma unroll
            for (int in_ = 0; in_ < 4; in_++) {
                int n = wn * 32 + in_ * 8 + group;
                int j0 = n * 20 + kb + quad;
                uint32_t b0 = sB32[j0], b1 = sB32[j0 + 4];
#pragma unroll
                for (int im = 0; im < 4; im++) {
                    mma_f16(acc[im][in_], ah[im], b0, b1);
                }
            }
        }
        __syncthreads();
    }

    // epilogue: fp16 store (rows padded to MPAD, no guards)
#pragma unroll
    for (int im = 0; im < 4; im++) {
        int r = brow + wm * 64 + im * 16 + group;
#pragma unroll
        for (int in_ = 0; in_ < 4; in_++) {
            int c = bcol + wn * 32 + in_ * 8 + quad * 2;
            __half2 lo = __floats2half2_rn(acc[im][in_][0], acc[im][in_][1]);
            __half2 hi = __floats2half2_rn(acc[im][in_][2], acc[im][in_][3]);
            *(__half2*)(g_h1 + (size_t)r * N + c) = lo;
            *(__half2*)(g_h1 + (size_t)(r + 8) * N + c) = hi;
        }
    }
}

// ---------------- aggregation (layers 1-3): bias+relu, fp16 in/out --------------
// 2 nodes per 128-thread block; 64 threads per node, each handles 8 features (16B)
__global__ void aggregate_h_kernel(const float* __restrict__ bias) {
    int i = blockIdx.x * 2 + (threadIdx.x >> 6);
    int t = threadIdx.x & 63;
    if (i >= N_NODES) return;
    int s = g_rowptr[i], e = g_rowptr[i + 1];
    float acc[8];
#pragma unroll
    for (int q = 0; q < 8; q++) acc[q] = 0.f;
    for (int p = s; p < e; p++) {
        int c = g_col[p];
        float v = g_val[p];
        uint4 raw = ((const uint4*)(g_h1 + (size_t)c * D_HID))[t];
        const __half2* hp = (const __half2*)&raw;
#pragma unroll
        for (int q = 0; q < 4; q++) {
            float2 f = __half22float2(hp[q]);
            acc[q * 2 + 0] += v * f.x;
            acc[q * 2 + 1] += v * f.y;
        }
    }
    float4 b0 = ((const float4*)bias)[t * 2];
    float4 b1 = ((const float4*)bias)[t * 2 + 1];
    acc[0] += b0.x; acc[1] += b0.y; acc[2] += b0.z; acc[3] += b0.w;
    acc[4] += b1.x; acc[5] += b1.y; acc[6] += b1.z; acc[7] += b1.w;
    uint4 outp;
    __half2* op = (__half2*)&outp;
#pragma unroll
    for (int q = 0; q < 4; q++) {
        op[q] = __floats2half2_rn(fmaxf(acc[q * 2 + 0], 0.f),
                                  fmaxf(acc[q * 2 + 1], 0.f));
    }
    ((uint4*)(g_a + (size_t)i * D_HID))[t] = outp;
}

// ---------------- aggregation (layer 4): bias, fp32 out, 2 nodes/block ----------
__global__ void aggregate_f32_kernel(const float* __restrict__ bias) {
    int i = blockIdx.x * 2 + (threadIdx.x >> 6);
    int t = threadIdx.x & 63;     // 4 features each (8B fp16 in, 16B fp32 out)
    if (i >= N_NODES) return;
    int s = g_rowptr[i], e = g_rowptr[i + 1];
    float4 acc = make_float4(0.f, 0.f, 0.f, 0.f);
    for (int p = s; p < e; p++) {
        int c = g_col[p];
        float v = g_val[p];
        uint2 raw = ((const uint2*)(g_h1 + (size_t)c * D_OUT))[t];
        const __half2* hp = (const __half2*)&raw;
        float2 f0 = __half22float2(hp[0]);
        float2 f1 = __half22float2(hp[1]);
        acc.x += v * f0.x; acc.y += v * f0.y; acc.z += v * f1.x; acc.w += v * f1.y;
    }
    float4 b = ((const float4*)bias)[t];
    acc.x += b.x; acc.y += b.y; acc.z += b.z; acc.w += b.w;
    ((float4*)(g_h2 + (size_t)i * D_OUT))[t] = acc;
}

// ---------------- pooling + L2 normalize (reads g_h2) ----------------
__global__ void pool_kernel() {
    __shared__ float red[256];
    int g = blockIdx.x, t = threadIdx.x;
    int s = g_goff[g], e = g_goff[g + 1];
    float acc = 0.f;
    for (int n = s; n < e; n++) acc += g_h2[(size_t)n * D_OUT + t];
    float cnt = (float)(e - s);
    float mean = acc / fmaxf(cnt, 1.f);
    red[t] = mean * mean;
    __syncthreads();
    for (int off = 128; off > 0; off >>= 1) {
        if (t < off) red[t] += red[t + off];
        __syncthreads();
    }
    float nrm = sqrtf(red[0]);
    g_pool[g * D_OUT + t] = mean / fmaxf(nrm, 1e-12f);
}

// ---------------- classifier MLP head ----------------
__global__ void mlp_kernel(const float* __restrict__ vec,
                           const float* __restrict__ cW1, const float* __restrict__ cb1,
                           const float* __restrict__ cW2, const float* __restrict__ cb2,
                           const float* __restrict__ cW3, const float* __restrict__ cb3,
                           float* __restrict__ out) {
    __shared__ float comb[512];
    __shared__ float z1[256];
    __shared__ float z2[64];
    int g = blockIdx.x, t = threadIdx.x;   // 256 threads
    comb[t] = g_pool[g * 256 + t];
    comb[256 + t] = vec[g * 256 + t];
    __syncthreads();
    float s1 = cb1[t];
    for (int k = 0; k < 512; k++) s1 += comb[k] * cW1[k * 256 + t];
    z1[t] = fmaxf(s1, 0.f);
    __syncthreads();
    if (t < 64) {
        float s2 = cb2[t];
        for (int k = 0; k < 256; k++) s2 += z1[k] * cW2[k * 64 + t];
        z2[t] = fmaxf(s2, 0.f);
    }
    __syncthreads();
    if (t == 0) {
        float s3 = cb3[0];
        for (int k = 0; k < 64; k++) s3 += z2[k] * cW3[k];
        out[g] = 1.f / (1.f + expf(-s3));
    }
}

// ---------------- launch ----------------
extern "C" void kernel_launch(void* const* d_in, const int* in_sizes, int n_in,
                              void* d_out, int out_size) {
    const float* x    = (const float*)d_in[0];
    const int*   ei   = (const int*)d_in[1];   // [2, E] int32
    const int*   bat  = (const int*)d_in[2];
    const float* vec  = (const float*)d_in[3];
    const float* W1 = (const float*)d_in[4],  *b1 = (const float*)d_in[5];
    const float* W2 = (const float*)d_in[6],  *b2 = (const float*)d_in[7];
    const float* W3 = (const float*)d_in[8],  *b3 = (const float*)d_in[9];
    const float* W4 = (const float*)d_in[10], *b4 = (const float*)d_in[11];
    const float* cW1 = (const float*)d_in[12], *cb1 = (const float*)d_in[13];
    const float* cW2 = (const float*)d_in[14], *cb2 = (const float*)d_in[15];
    const float* cW3 = (const float*)d_in[16], *cb3 = (const float*)d_in[17];
    float* out = (float*)d_out;

    const int* src = ei;
    const int* dst = ei + N_EDGES;

    cudaFuncSetAttribute(mma_gemm_kernel,
                         cudaFuncAttributeMaxDynamicSharedMemorySize, SMEM_BYTES);

    // side stream + events for capture-fork (created once; no device allocation)
    static cudaStream_t s_side = nullptr;
    static cudaEvent_t ev_fork = nullptr, ev_join = nullptr;
    if (s_side == nullptr) {
        cudaStreamCreateWithFlags(&s_side, cudaStreamNonBlocking);
        cudaEventCreateWithFlags(&ev_fork, cudaEventDisableTiming);
        cudaEventCreateWithFlags(&ev_join, cudaEventDisableTiming);
    }

    // fork: side stream runs CSR preprocessing + wconv2-4, overlapping GEMM1 path
    cudaEventRecord(ev_fork, 0);
    cudaStreamWaitEvent(s_side, ev_fork, 0);

    init_kernel<<<(N_NODES + 255) / 256, 256, 0, s_side>>>();
    hist_kernel<<<(N_EDGES + 255) / 256, 256, 0, s_side>>>(dst, bat);
    scan_part_kernel<<<SCAN_BLKS, 256, 0, s_side>>>();
    scan_mid_kernel<<<1, 128, 0, s_side>>>();
    scan_add_kernel<<<SCAN_BLKS, 256, 0, s_side>>>();
    fill_csr_kernel<<<(N_TOT + 255) / 256, 256, 0, s_side>>>(src, dst);
    wconv_kernel<<<(D_HID * D_HID + 255) / 256, 256, 0, s_side>>>(W2, D_HID, D_HID, 2);
    wconv_kernel<<<(D_HID * D_HID + 255) / 256, 256, 0, s_side>>>(W3, D_HID, D_HID, 3);
    wconv_kernel<<<(D_HID * D_OUT + 255) / 256, 256, 0, s_side>>>(W4, D_HID, D_OUT, 4);
    cudaEventRecord(ev_join, s_side);

    // main stream: conversions for layer 1 + GEMM1
    xconv_kernel<<<(N_NODES * D_IN + 255) / 256, 256>>>(x);
    wconv_kernel<<<(D_IN * D_HID + 255) / 256, 256>>>(W1, D_IN, D_HID, 1);

    dim3 blk(256);
    int gy = MPAD / 128;   // 79
    mma_gemm_kernel<<<dim3(D_HID / 128, gy), blk, SMEM_BYTES>>>(0, 1, D_IN, D_HID);

    // join: aggregate needs CSR (side) + GEMM1 output (main)
    cudaStreamWaitEvent(0, ev_join, 0);

    aggregate_h_kernel<<<(N_NODES + 1) / 2, 128>>>(b1);
    // layer 2
    mma_gemm_kernel<<<dim3(D_HID / 128, gy), blk, SMEM_BYTES>>>(1, 2, D_HID, D_HID);
    aggregate_h_kernel<<<(N_NODES + 1) / 2, 128>>>(b2);
    // layer 3
    mma_gemm_kernel<<<dim3(D_HID / 128, gy), blk, SMEM_BYTES>>>(1, 3, D_HID, D_HID);
    aggregate_h_kernel<<<(N_NODES + 1) / 2, 128>>>(b3);
    // layer 4
    mma_gemm_kernel<<<dim3(D_OUT / 128, gy), blk, SMEM_BYTES>>>(1, 4, D_HID, D_OUT);
    aggregate_f32_kernel<<<(N_NODES + 1) / 2, 128>>>(b4);

    // pooling + normalize + head
    pool_kernel<<<G, 256>>>();
    mlp_kernel<<<G, 256>>>(vec, cW1, cb1, cW2, cb2, cW3, cb3, out);
}